// round 1
// baseline (speedup 1.0000x reference)
#include <cuda_runtime.h>
#include <cuda_bf16.h>
#include <math.h>

#define NN 50000
#define EE 800000
#define IN_DIM 128
#define FD 64
#define CAT 192
#define OUTD 16

__device__ __align__(16) float g_deg[3 * NN];
__device__ __align__(16) float g_selfn[3 * NN];
__device__ __align__(16) float g_norm[3 * EE];
__device__ __align__(16) float g_h[NN * FD];
__device__ __align__(16) float g_h2[NN * FD];
__device__ __align__(16) float g_hcat[(size_t)NN * CAT];

__global__ void k_init_deg() {
    int i = blockIdx.x * blockDim.x + threadIdx.x;
    if (i < 3 * NN) g_deg[i] = 1.0f;
}

__global__ void k_deg_accum(const int* __restrict__ col0,
                            const int* __restrict__ col1,
                            const int* __restrict__ col2,
                            const float* __restrict__ w1,
                            const float* __restrict__ w2) {
    int e = blockIdx.x * blockDim.x + threadIdx.x;
    if (e >= EE) return;
    atomicAdd(&g_deg[col0[e]], 1.0f);
    atomicAdd(&g_deg[NN + col1[e]], w1[e]);
    atomicAdd(&g_deg[2 * NN + col2[e]], w2[e]);
}

__global__ void k_dis() {
    int i = blockIdx.x * blockDim.x + threadIdx.x;
    if (i >= 3 * NN) return;
    float d = g_deg[i];
    float dis = rsqrtf(d);
    g_deg[i] = dis;
    g_selfn[i] = dis * dis;
}

__global__ void k_norm(const int* __restrict__ r0, const int* __restrict__ c0,
                       const int* __restrict__ r1, const int* __restrict__ c1,
                       const int* __restrict__ r2, const int* __restrict__ c2,
                       const float* __restrict__ w1, const float* __restrict__ w2) {
    int e = blockIdx.x * blockDim.x + threadIdx.x;
    if (e >= EE) return;
    const float* dis0 = g_deg;
    const float* dis1 = g_deg + NN;
    const float* dis2 = g_deg + 2 * NN;
    g_norm[e]          = dis0[r0[e]] * dis0[c0[e]];
    g_norm[EE + e]     = dis1[r1[e]] * w1[e] * dis1[c1[e]];
    g_norm[2 * EE + e] = dis2[r2[e]] * w2[e] * dis2[c2[e]];
}

template <int K, bool RELU>
__global__ void k_gemm(const float* __restrict__ A, const float* __restrict__ W,
                       float* __restrict__ C) {
    __shared__ float Ws[64][65];
    __shared__ float As[32][64];
    const int row0 = blockIdx.x * 32;
    const int f = threadIdx.x & 63;
    const int rq = threadIdx.x >> 6;

    float acc[8];
#pragma unroll
    for (int r = 0; r < 8; r++) acc[r] = 0.0f;

    for (int kc = 0; kc < K; kc += 64) {
        for (int i = threadIdx.x; i < 64 * 64; i += 256) {
            int ff = i >> 6, kk = i & 63;
            Ws[kk][ff] = W[ff * K + kc + kk];
        }
        for (int i = threadIdx.x; i < 32 * 64; i += 256) {
            int r = i >> 6, kk = i & 63;
            int row = row0 + r;
            float v = (row < NN) ? A[(size_t)row * K + kc + kk] : 0.0f;
            if (RELU) v = fmaxf(v, 0.0f);
            As[r][kk] = v;
        }
        __syncthreads();
#pragma unroll 8
        for (int kk = 0; kk < 64; kk++) {
            float wv = Ws[kk][f];
#pragma unroll
            for (int r = 0; r < 8; r++)
                acc[r] = fmaf(wv, As[rq * 8 + r][kk], acc[r]);
        }
        __syncthreads();
    }
#pragma unroll
    for (int r = 0; r < 8; r++) {
        int row = row0 + rq * 8 + r;
        if (row < NN) C[(size_t)row * FD + f] = acc[r];
    }
}

__global__ void k_init_hcat(const float* __restrict__ h, const float* __restrict__ bias) {
    int idx = blockIdx.x * blockDim.x + threadIdx.x;
    if (idx >= NN * FD) return;
    int i = idx >> 6;
    int f = idx & 63;
    float hv = h[idx];
    float b = bias[f];
    size_t base = (size_t)i * CAT + f;
    g_hcat[base]       = b + g_selfn[i] * hv;
    g_hcat[base + 64]  = b + g_selfn[NN + i] * hv;
    g_hcat[base + 128] = b + g_selfn[2 * NN + i] * hv;
}

__global__ void k_scatter(const int* __restrict__ rows, const int* __restrict__ cols,
                          const float* __restrict__ norm, const float* __restrict__ h,
                          int setoff) {
    int idx = blockIdx.x * blockDim.x + threadIdx.x;
    int e = idx >> 4;
    if (e >= EE) return;
    int t = idx & 15;
    int r = rows[e];
    int c = cols[e];
    float nv = norm[e];
    float4 hv = *reinterpret_cast<const float4*>(h + (size_t)r * FD + t * 4);
    float a = nv * hv.x, b = nv * hv.y, cc = nv * hv.z, d = nv * hv.w;
    float* dst = g_hcat + (size_t)c * CAT + setoff + t * 4;
    asm volatile("red.global.add.v4.f32 [%0], {%1, %2, %3, %4};"
                 :: "l"(dst), "f"(a), "f"(b), "f"(cc), "f"(d) : "memory");
}

__global__ void k_final(const float* __restrict__ convw, const float* __restrict__ convb,
                        float* __restrict__ out) {
    __shared__ float Ws[CAT * OUTD];
    for (int i = threadIdx.x; i < CAT * OUTD; i += 256) {
        int j = i / CAT, k = i % CAT;
        Ws[k * OUTD + j] = convw[(size_t)j * CAT + k];
    }
    __syncthreads();

    int rl = threadIdx.x >> 4;
    int j = threadIdx.x & 15;
    int row = blockIdx.x * 16 + rl;
    if (row >= NN) return;

    const float4* hr = reinterpret_cast<const float4*>(g_hcat + (size_t)row * CAT);
    float acc = convb[j];
#pragma unroll 12
    for (int k4 = 0; k4 < CAT / 4; k4++) {
        float4 hv = hr[k4];
        int k = k4 * 4;
        acc = fmaf(fmaxf(hv.x, 0.0f), Ws[(k + 0) * OUTD + j], acc);
        acc = fmaf(fmaxf(hv.y, 0.0f), Ws[(k + 1) * OUTD + j], acc);
        acc = fmaf(fmaxf(hv.z, 0.0f), Ws[(k + 2) * OUTD + j], acc);
        acc = fmaf(fmaxf(hv.w, 0.0f), Ws[(k + 3) * OUTD + j], acc);
    }
    float m = acc;
#pragma unroll
    for (int o = 8; o > 0; o >>= 1)
        m = fmaxf(m, __shfl_xor_sync(0xffffffff, m, o, 16));
    float ex = __expf(acc - m);
    float s = ex;
#pragma unroll
    for (int o = 8; o > 0; o >>= 1)
        s += __shfl_xor_sync(0xffffffff, s, o, 16);
    out[(size_t)row * OUTD + j] = acc - m - __logf(s);
}

extern "C" void kernel_launch(void* const* d_in, const int* in_sizes, int n_in,
                              void* d_out, int out_size) {
    const float* x     = (const float*)d_in[0];
    const int*   ei    = (const int*)d_in[1];
    const int*   e_in  = (const int*)d_in[2];
    const int*   e_out = (const int*)d_in[3];
    const float* in_w  = (const float*)d_in[4];
    const float* out_w = (const float*)d_in[5];
    const float* lin1  = (const float*)d_in[6];
    const float* lin2  = (const float*)d_in[7];
    const float* b1    = (const float*)d_in[8];
    const float* b2    = (const float*)d_in[9];
    const float* convw = (const float*)d_in[10];
    const float* convb = (const float*)d_in[11];
    float* out = (float*)d_out;
    (void)in_sizes; (void)n_in; (void)out_size;

    const int* r0 = ei;    const int* c0 = ei + EE;
    const int* r1 = e_in;  const int* c1 = e_in + EE;
    const int* r2 = e_out; const int* c2 = e_out + EE;

    static float *p_h = nullptr, *p_h2 = nullptr, *p_norm = nullptr, *p_hcat = nullptr;
    if (!p_h) {
        cudaGetSymbolAddress((void**)&p_h, g_h);
        cudaGetSymbolAddress((void**)&p_h2, g_h2);
        cudaGetSymbolAddress((void**)&p_norm, g_norm);
        cudaGetSymbolAddress((void**)&p_hcat, g_hcat);
    }

    k_init_deg<<<(3 * NN + 255) / 256, 256>>>();
    k_deg_accum<<<(EE + 255) / 256, 256>>>(c0, c1, c2, in_w, out_w);
    k_dis<<<(3 * NN + 255) / 256, 256>>>();
    k_norm<<<(EE + 255) / 256, 256>>>(r0, c0, r1, c1, r2, c2, in_w, out_w);

    const int gemm_grid = (NN + 31) / 32;
    const int scat_grid = (EE * 16 + 255) / 256;

    k_gemm<IN_DIM, false><<<gemm_grid, 256>>>(x, lin1, p_h);
    k_init_hcat<<<(NN * FD + 255) / 256, 256>>>(p_h, b1);
    k_scatter<<<scat_grid, 256>>>(r0, c0, p_norm,          p_h, 0);
    k_scatter<<<scat_grid, 256>>>(r1, c1, p_norm + EE,     p_h, 64);
    k_scatter<<<scat_grid, 256>>>(r2, c2, p_norm + 2 * EE, p_h, 128);

    k_gemm<CAT, true><<<gemm_grid, 256>>>(p_hcat, lin2, p_h2);
    k_init_hcat<<<(NN * FD + 255) / 256, 256>>>(p_h2, b2);
    k_scatter<<<scat_grid, 256>>>(r0, c0, p_norm,          p_h2, 0);
    k_scatter<<<scat_grid, 256>>>(r1, c1, p_norm + EE,     p_h2, 64);
    k_scatter<<<scat_grid, 256>>>(r2, c2, p_norm + 2 * EE, p_h2, 128);

    k_final<<<(NN + 15) / 16, 256>>>(convw, convb, out);
}